// round 16
// baseline (speedup 1.0000x reference)
#include <cuda_runtime.h>
#include <cuda_fp16.h>
#include <cstdint>

// Problem constants (fixed shapes per reference)
#define N_NODES 100000
#define F_IN    256
#define H_DIM   128
#define D_DIM   64
#define MAX_E   1700000
#define NSPLIT  50048          // epilogue chunk boundary (multiple of 128)

// ---------------- scratch (device globals; no allocation allowed) -------------
__device__ __align__(16) int    g_cnt [N_NODES];             // per-dst edge count / fill cursor
__device__ __align__(16) int    g_row [N_NODES + 1];         // CSR row offsets
__device__ __align__(16) float  g_dinv[N_NODES];             // rsqrt(deg) incl self-loop
__device__ __align__(16) int2   g_csr [MAX_E];               // {src, norm-as-int-bits}
__device__ __align__(16) __half g_h1  [N_NODES * H_DIM];     // x @ W1        (fp16)
__device__ __align__(16) __half g_h2  [N_NODES * H_DIM];     // relu(agg1+b1) (fp16)
__device__ __align__(16) __half g_agg2[N_NODES * H_DIM];     // aggregated h2 (fp16)
__device__ __align__(16) float  g_bc  [128];                 // [bmu | bvar]
// Precomputed B fragments for m16n8k16 fp16 mma (2-split hi/lo):
//   index = (kstep16*16 + ntile)*32 + lane, value = {bh0, bh1, bl0, bl1} (f16x2 each)
__device__ __align__(16) uint4 g_Bf1[16 * 16 * 32];          // W1:  K=256 -> 16 ksteps
__device__ __align__(16) uint4 g_Bf2[ 8 * 16 * 32];          // Wc:  K=128 ->  8 ksteps

// ---------------- fp16 pack/unpack helpers ---------------------------------------
__device__ __forceinline__ float4 h4_to_f4(uint2 u) {
    float2 f0 = __half22float2(*(const __half2*)&u.x);
    float2 f1 = __half22float2(*(const __half2*)&u.y);
    return make_float4(f0.x, f0.y, f1.x, f1.y);
}
__device__ __forceinline__ uint2 f4_to_h4(float4 v) {
    __half2 h0 = __floats2half2_rn(v.x, v.y);
    __half2 h1 = __floats2half2_rn(v.z, v.w);
    uint2 u;
    u.x = *(const uint32_t*)&h0;
    u.y = *(const uint32_t*)&h1;
    return u;
}
__device__ __forceinline__ uint32_t pack_h2(float x, float y) {
    __half2 h = __floats2half2_rn(x, y);
    return *(const uint32_t*)&h;
}

// ---------------- CSR build ------------------------------------------------------
__global__ void zero_cnt_kernel() {
    int i = blockIdx.x * blockDim.x + threadIdx.x;
    if (i < N_NODES) g_cnt[i] = 0;
}

__global__ void count_kernel(const int* __restrict__ dst, int E) {
    int i = blockIdx.x * blockDim.x + threadIdx.x;
    if (i < E) atomicAdd(&g_cnt[dst[i]], 1);
}

// Single-block exclusive scan over g_cnt -> g_row, plus dinv, plus cnt reset.
__global__ void scan_kernel() {            // <<<1, 1024>>>
    __shared__ int warp_sums[32];
    __shared__ int s_carry;
    const int tid = threadIdx.x, lane = tid & 31, wid = tid >> 5;
    if (tid == 0) s_carry = 0;
    __syncthreads();
    for (int base = 0; base < N_NODES; base += 1024) {
        int i = base + tid;
        int v = (i < N_NODES) ? g_cnt[i] : 0;
        if (i < N_NODES) {
            g_dinv[i] = rsqrtf((float)v + 1.0f);   // +1 self-loop
            g_cnt[i] = 0;                           // reset as fill cursor
        }
        int x = v;
#pragma unroll
        for (int off = 1; off < 32; off <<= 1) {
            int t = __shfl_up_sync(0xffffffffu, x, off);
            if (lane >= off) x += t;
        }
        if (lane == 31) warp_sums[wid] = x;
        __syncthreads();
        if (wid == 0) {
            int y = warp_sums[lane];
#pragma unroll
            for (int off = 1; off < 32; off <<= 1) {
                int t = __shfl_up_sync(0xffffffffu, y, off);
                if (lane >= off) y += t;
            }
            warp_sums[lane] = y;
        }
        __syncthreads();
        int warp_off = (wid == 0) ? 0 : warp_sums[wid - 1];
        if (i < N_NODES) g_row[i] = s_carry + warp_off + x - v;   // exclusive
        __syncthreads();
        if (tid == 1023) s_carry += warp_sums[31];
        __syncthreads();
    }
    if (threadIdx.x == 0) g_row[N_NODES] = s_carry;
}

__global__ void fill_kernel(const int* __restrict__ src, const int* __restrict__ dst, int E) {
    int e = blockIdx.x * blockDim.x + threadIdx.x;
    if (e >= E) return;
    int s = src[e], d = dst[e];
    int pos = g_row[d] + atomicAdd(&g_cnt[d], 1);
    g_csr[pos] = make_int2(s, __float_as_int(g_dinv[s] * g_dinv[d]));
}

// ---------------- fp16 mma helper -------------------------------------------------
__device__ __forceinline__ void mma_f16(float* d, const uint32_t* a, uint32_t b0, uint32_t b1) {
    asm volatile(
        "mma.sync.aligned.m16n8k16.row.col.f32.f16.f16.f32 "
        "{%0,%1,%2,%3}, {%4,%5,%6,%7}, {%8,%9}, {%0,%1,%2,%3};"
        : "+f"(d[0]), "+f"(d[1]), "+f"(d[2]), "+f"(d[3])
        : "r"(a[0]), "r"(a[1]), "r"(a[2]), "r"(a[3]), "r"(b0), "r"(b1));
}

// ---------------- B fragment precompute ------------------------------------------
// m16n8k16 B fragment (col-major, B[k][n]): lane -> gid=lane>>2, tig=lane&3;
// b0 = {B[s*16+2tig][n], B[s*16+2tig+1][n]}, b1 = {B[s*16+8+2tig][n], B[+1][n]}.
__device__ __forceinline__ void pack_bfrag(uint4* out, int i, float b00, float b01,
                                           float b10, float b11) {
    __half h00 = __float2half_rn(b00), h01 = __float2half_rn(b01);
    __half h10 = __float2half_rn(b10), h11 = __float2half_rn(b11);
    uint32_t bh0 = pack_h2(__half2float(h00), __half2float(h01));
    uint32_t bh1 = pack_h2(__half2float(h10), __half2float(h11));
    uint32_t bl0 = pack_h2(b00 - __half2float(h00), b01 - __half2float(h01));
    uint32_t bl1 = pack_h2(b10 - __half2float(h10), b11 - __half2float(h11));
    out[i] = make_uint4(bh0, bh1, bl0, bl1);
}

__global__ void pack_bfrag1_kernel(const float* __restrict__ W1) {
    int i = blockIdx.x * blockDim.x + threadIdx.x;   // 0 .. 16*16*32-1
    if (i >= 16 * 16 * 32) return;
    int lane = i & 31, nt = (i >> 5) & 15, s = i >> 9;
    int gid = lane >> 2, tig = lane & 3;
    int n = nt * 8 + gid;
    int k0 = s * 16 + 2 * tig;
    int k1 = k0 + 8;
    pack_bfrag(g_Bf1, i,
               W1[(k0 + 0) * 128 + n], W1[(k0 + 1) * 128 + n],
               W1[(k1 + 0) * 128 + n], W1[(k1 + 1) * 128 + n]);
}

__global__ void pack_bfrag2_kernel(const float* __restrict__ Wmu, const float* __restrict__ Wvar,
                                   const float* __restrict__ bmu, const float* __restrict__ bvar) {
    int i = blockIdx.x * blockDim.x + threadIdx.x;
    if (i < 128) g_bc[i] = (i < D_DIM) ? bmu[i] : bvar[i - D_DIM];
    if (i >= 8 * 16 * 32) return;
    int lane = i & 31, nt = (i >> 5) & 15, s = i >> 9;
    int gid = lane >> 2, tig = lane & 3;
    int n = nt * 8 + gid;
    int k0 = s * 16 + 2 * tig;
    int k1 = k0 + 8;
    auto W = [&](int k) {
        return (n < D_DIM) ? Wmu[k * D_DIM + n] : Wvar[k * D_DIM + (n - D_DIM)];
    };
    pack_bfrag(g_Bf2, i, W(k0), W(k0 + 1), W(k1), W(k1 + 1));
}

// ---------------- 2-split FP16 tensor-core GEMM: C[M,128] = A[M,K] @ B[K,128] -----
// Block 128x128, 256 threads = 8 warps as 2(m) x 4(n); warp tile 64x32.
// BK=16 double-buffered A in smem, [kpair][row] layout (R13-proven path).
// MODE 0: A = x (fp32, 2-split Ah+Al, 3 mma) -> g_h1 (fp16).
// MODE 1: A = g_agg2 (fp16 exact: Al=0, 2 mma), +bias -> mu|sigma (fp32).
template <int MODE>
__global__ void __launch_bounds__(256, 2)
tgemm_kernel(const float* __restrict__ Ap,
             float* __restrict__ outMu, float* __restrict__ outSig,
             int row_base, int M, int K) {
    __shared__ __align__(16) uint32_t Ah[2][8][136];   // [buf][kpair][row] f16x2
    __shared__ __align__(16) uint32_t Al[2][8][136];   // MODE 0 only

    const uint4* Bf = (MODE == 0) ? g_Bf1 : g_Bf2;

    const int tid    = threadIdx.x;
    const int lane   = tid & 31;
    const int wid    = tid >> 5;
    const int warp_m = wid >> 2;      // 0..1 (64 rows each)
    const int warp_n = wid & 3;       // 0..3 (32 cols each)
    const int gid    = lane >> 2;     // 0..7
    const int tig    = lane & 3;      // 0..3
    const int row0   = row_base + blockIdx.x * 128;

    float acc[4][4][4];
#pragma unroll
    for (int mt = 0; mt < 4; mt++)
#pragma unroll
        for (int nt = 0; nt < 4; nt++)
#pragma unroll
            for (int r = 0; r < 4; r++) acc[mt][nt][r] = 0.0f;

    // BK=16 tile: thread stages row r = tid>>1, k-octet q8 = (tid&1)*8 (kpairs kp0..+3).
    auto load_tile = [&](int k0, int buf) {
        int r = tid >> 1, q8 = (tid & 1) * 8;
        int kp0 = q8 >> 1;                       // 0 or 4
        int gr = row0 + r;
        if (MODE == 0) {
            float4 va0 = make_float4(0.f, 0.f, 0.f, 0.f);
            float4 va1 = make_float4(0.f, 0.f, 0.f, 0.f);
            if (gr < M) {
                const float* ap = &Ap[(size_t)gr * K + k0 + q8];
                va0 = *(const float4*)&ap[0];
                va1 = *(const float4*)&ap[4];
            }
            float av[8] = {va0.x, va0.y, va0.z, va0.w, va1.x, va1.y, va1.z, va1.w};
#pragma unroll
            for (int jp = 0; jp < 4; jp++) {
                float x0 = av[2 * jp], x1 = av[2 * jp + 1];
                __half h0 = __float2half_rn(x0), h1 = __float2half_rn(x1);
                Ah[buf][kp0 + jp][r] = pack_h2(__half2float(h0), __half2float(h1));
                Al[buf][kp0 + jp][r] = pack_h2(x0 - __half2float(h0), x1 - __half2float(h1));
            }
        } else {
            uint4 v = make_uint4(0u, 0u, 0u, 0u);
            if (gr < M) v = *(const uint4*)&g_agg2[(size_t)gr * K + k0 + q8];
            Ah[buf][kp0 + 0][r] = v.x;
            Ah[buf][kp0 + 1][r] = v.y;
            Ah[buf][kp0 + 2][r] = v.z;
            Ah[buf][kp0 + 3][r] = v.w;
        }
    };

    const int steps = K / 16;
    load_tile(0, 0);
    __syncthreads();

    const uint4* BfW = Bf + (size_t)warp_n * 4 * 32 + lane;   // + s*16*32 + nt*32

    for (int s = 0; s < steps; s++) {
        uint4 fb[4];
#pragma unroll
        for (int nt = 0; nt < 4; nt++)
            fb[nt] = __ldg(&BfW[(size_t)s * 16 * 32 + nt * 32]);

        if (s + 1 < steps) load_tile((s + 1) * 16, (s + 1) & 1);
        const int cb = s & 1;

        uint32_t fah[4][4], fal[4][4];
#pragma unroll
        for (int mt = 0; mt < 4; mt++) {
            int m0 = warp_m * 64 + mt * 16;
            fah[mt][0] = Ah[cb][tig][m0 + gid];
            fah[mt][1] = Ah[cb][tig][m0 + 8 + gid];
            fah[mt][2] = Ah[cb][tig + 4][m0 + gid];
            fah[mt][3] = Ah[cb][tig + 4][m0 + 8 + gid];
            if (MODE == 0) {
                fal[mt][0] = Al[cb][tig][m0 + gid];
                fal[mt][1] = Al[cb][tig][m0 + 8 + gid];
                fal[mt][2] = Al[cb][tig + 4][m0 + gid];
                fal[mt][3] = Al[cb][tig + 4][m0 + 8 + gid];
            }
        }
#pragma unroll
        for (int mt = 0; mt < 4; mt++)
#pragma unroll
            for (int nt = 0; nt < 4; nt++) {
                mma_f16(acc[mt][nt], fah[mt], fb[nt].x, fb[nt].y);       // Ah*Bh
                mma_f16(acc[mt][nt], fah[mt], fb[nt].z, fb[nt].w);       // Ah*Bl
                if (MODE == 0)
                    mma_f16(acc[mt][nt], fal[mt], fb[nt].x, fb[nt].y);   // Al*Bh
            }
        __syncthreads();
    }

    // Epilogue. c0,c1 -> row gid, cols 2tig,2tig+1; c2,c3 -> row gid+8.
#pragma unroll
    for (int mt = 0; mt < 4; mt++) {
#pragma unroll
        for (int nt = 0; nt < 4; nt++) {
            int col = warp_n * 32 + nt * 8 + 2 * tig;
            int ra  = row0 + warp_m * 64 + mt * 16 + gid;
            int rb  = ra + 8;
            if (MODE == 0) {
                if (ra < M) *(__half2*)&g_h1[(size_t)ra * 128 + col] =
                    __floats2half2_rn(acc[mt][nt][0], acc[mt][nt][1]);
                if (rb < M) *(__half2*)&g_h1[(size_t)rb * 128 + col] =
                    __floats2half2_rn(acc[mt][nt][2], acc[mt][nt][3]);
            } else {
                float b0 = g_bc[col], b1 = g_bc[col + 1];
                float* baseA;
                float* baseB;
                if (col < 64) {
                    baseA = outMu + (size_t)ra * D_DIM + col;
                    baseB = outMu + (size_t)rb * D_DIM + col;
                } else {
                    baseA = outSig + (size_t)ra * D_DIM + (col - 64);
                    baseB = outSig + (size_t)rb * D_DIM + (col - 64);
                }
                if (ra < M) *(float2*)baseA =
                    make_float2(acc[mt][nt][0] + b0, acc[mt][nt][1] + b1);
                if (rb < M) *(float2*)baseB =
                    make_float2(acc[mt][nt][2] + b0, acc[mt][nt][3] + b1);
            }
        }
    }
}

// ---------------- CSR gather-aggregate (fp16 h rows, fp32 accumulate) -------------
// One warp per node over node range [n0, n1); each lane covers 4 features.
// LAYER 0: reads g_h1, writes g_h2 = relu(agg + b1) as fp16 (relu fused)
// LAYER 1: reads g_h2, writes g_agg2 as fp16 (feeds GEMM2).
template <int LAYER>
__global__ void __launch_bounds__(256)
aggregate_kernel(const float* __restrict__ b1, int n0, int n1) {
    int n    = n0 + ((blockIdx.x * 256 + threadIdx.x) >> 5);
    int lane = threadIdx.x & 31;
    if (n >= n1) return;

    const __half* h = (LAYER == 0) ? g_h1 : g_h2;

    float di = g_dinv[n];
    float d2 = di * di;
    float4 acc = h4_to_f4(__ldg(&((const uint2*)(h + (size_t)n * 128))[lane]));
    acc.x *= d2; acc.y *= d2; acc.z *= d2; acc.w *= d2;

    int r0 = g_row[n], r1 = g_row[n + 1];
    for (int base = r0; base < r1; base += 32) {
        int rem = min(r1 - base, 32);
        int2 ent = make_int2(0, 0);
        if (lane < rem) ent = g_csr[base + lane];

        int k = 0;
        for (; k + 4 <= rem; k += 4) {
            int   s0 = __shfl_sync(0xffffffffu, ent.x, k + 0);
            int   s1 = __shfl_sync(0xffffffffu, ent.x, k + 1);
            int   s2 = __shfl_sync(0xffffffffu, ent.x, k + 2);
            int   s3 = __shfl_sync(0xffffffffu, ent.x, k + 3);
            float w0 = __int_as_float(__shfl_sync(0xffffffffu, ent.y, k + 0));
            float w1 = __int_as_float(__shfl_sync(0xffffffffu, ent.y, k + 1));
            float w2 = __int_as_float(__shfl_sync(0xffffffffu, ent.y, k + 2));
            float w3 = __int_as_float(__shfl_sync(0xffffffffu, ent.y, k + 3));
            uint2 u0 = __ldg(&((const uint2*)(h + (size_t)s0 * 128))[lane]);
            uint2 u1 = __ldg(&((const uint2*)(h + (size_t)s1 * 128))[lane]);
            uint2 u2 = __ldg(&((const uint2*)(h + (size_t)s2 * 128))[lane]);
            uint2 u3 = __ldg(&((const uint2*)(h + (size_t)s3 * 128))[lane]);
            float4 v0 = h4_to_f4(u0);
            float4 v1 = h4_to_f4(u1);
            float4 v2 = h4_to_f4(u2);
            float4 v3 = h4_to_f4(u3);
            acc.x = fmaf(v0.x, w0, acc.x); acc.y = fmaf(v0.y, w0, acc.y);
            acc.z = fmaf(v0.z, w0, acc.z); acc.w = fmaf(v0.w, w0, acc.w);
            acc.x = fmaf(v1.x, w1, acc.x); acc.y = fmaf(v1.y, w1, acc.y);
            acc.z = fmaf(v1.z, w1, acc.z); acc.w = fmaf(v1.w, w1, acc.w);
            acc.x = fmaf(v2.x, w2, acc.x); acc.y = fmaf(v2.y, w2, acc.y);
            acc.z = fmaf(v2.z, w2, acc.z); acc.w = fmaf(v2.w, w2, acc.w);
            acc.x = fmaf(v3.x, w3, acc.x); acc.y = fmaf(v3.y, w3, acc.y);
            acc.z = fmaf(v3.z, w3, acc.z); acc.w = fmaf(v3.w, w3, acc.w);
        }
        for (; k < rem; k++) {
            int   s = __shfl_sync(0xffffffffu, ent.x, k);
            float w = __int_as_float(__shfl_sync(0xffffffffu, ent.y, k));
            float4 v = h4_to_f4(__ldg(&((const uint2*)(h + (size_t)s * 128))[lane]));
            acc.x = fmaf(v.x, w, acc.x); acc.y = fmaf(v.y, w, acc.y);
            acc.z = fmaf(v.z, w, acc.z); acc.w = fmaf(v.w, w, acc.w);
        }
    }

    if (LAYER == 0) {
        float4 b = ((const float4*)b1)[lane];
        acc.x = fmaxf(acc.x + b.x, 0.0f);
        acc.y = fmaxf(acc.y + b.y, 0.0f);
        acc.z = fmaxf(acc.z + b.z, 0.0f);
        acc.w = fmaxf(acc.w + b.w, 0.0f);
        ((uint2*)(g_h2 + (size_t)n * 128))[lane] = f4_to_h4(acc);
    } else {
        ((uint2*)(g_agg2 + (size_t)n * 128))[lane] = f4_to_h4(acc);
    }
}

// --------------------------------------------------------------------------------
extern "C" void kernel_launch(void* const* d_in, const int* in_sizes, int n_in,
                              void* d_out, int out_size) {
    const float* x    = (const float*)d_in[0];
    const int*   ei   = (const int*)d_in[1];     // edge_index: int32
    const float* W1   = (const float*)d_in[2];
    const float* b1   = (const float*)d_in[3];
    const float* Wmu  = (const float*)d_in[4];
    const float* bmu  = (const float*)d_in[5];
    const float* Wvar = (const float*)d_in[6];
    const float* bvar = (const float*)d_in[7];

    const int E = in_sizes[1] / 2;
    const int* src = ei;
    const int* dst = ei + E;

    float* outMu  = (float*)d_out;
    float* outSig = (float*)d_out + (size_t)N_NODES * D_DIM;

    auto aggBlocks = [](int n0, int n1) { return ((n1 - n0) * 32 + 255) / 256; };

    // Side stream + fork/join events: created once, reused every call (the
    // captured graph is identical call-to-call; no device memory involved).
    static cudaStream_t s_side = nullptr;
    static cudaEvent_t  s_evFork = nullptr, s_evJoin = nullptr;
    static cudaEvent_t  s_evAggA = nullptr, s_evTail = nullptr;
    if (s_side == nullptr) {
        cudaStreamCreateWithFlags(&s_side, cudaStreamNonBlocking);
        cudaEventCreateWithFlags(&s_evFork, cudaEventDisableTiming);
        cudaEventCreateWithFlags(&s_evJoin, cudaEventDisableTiming);
        cudaEventCreateWithFlags(&s_evAggA, cudaEventDisableTiming);
        cudaEventCreateWithFlags(&s_evTail, cudaEventDisableTiming);
    }

    // Fork: CSR chain + projection pack on side stream, GEMM1 on main stream.
    cudaEventRecord(s_evFork, 0);
    cudaStreamWaitEvent(s_side, s_evFork, 0);

    pack_bfrag1_kernel<<<(16 * 16 * 32 + 255) / 256, 256>>>(W1);            // #1 main
    zero_cnt_kernel   <<<(N_NODES + 255) / 256, 256, 0, s_side>>>();        // #2 side
    count_kernel      <<<(E + 255) / 256, 256, 0, s_side>>>(dst, E);        // #3 side

    // #4 (ncu capture slot): layer-1 fp16 GEMM (h1) — overlaps the CSR chain
    tgemm_kernel<0><<<(N_NODES + 127) / 128, 256>>>(x, nullptr, nullptr, 0, N_NODES, F_IN);

    scan_kernel       <<<1, 1024, 0, s_side>>>();                           // side
    fill_kernel       <<<(E + 255) / 256, 256, 0, s_side>>>(src, dst, E);   // side
    pack_bfrag2_kernel<<<(8 * 16 * 32 + 255) / 256, 256, 0, s_side>>>(Wmu, Wvar, bmu, bvar);

    // Join: aggregates need both h1 (main) and CSR (side).
    cudaEventRecord(s_evJoin, s_side);
    cudaStreamWaitEvent(0, s_evJoin, 0);

    // layer-1 aggregate + fused relu (writes h2, fp16) — all nodes
    aggregate_kernel<0><<<aggBlocks(0, N_NODES), 256>>>(b1, 0, N_NODES);

    // layer-2 aggregate, chunk A; then tgemm1-A on side stream overlaps chunk B.
    aggregate_kernel<1><<<aggBlocks(0, NSPLIT), 256>>>(nullptr, 0, NSPLIT);
    cudaEventRecord(s_evAggA, 0);
    aggregate_kernel<1><<<aggBlocks(NSPLIT, N_NODES), 256>>>(nullptr, NSPLIT, N_NODES);

    cudaStreamWaitEvent(s_side, s_evAggA, 0);
    tgemm_kernel<1><<<NSPLIT / 128, 256, 0, s_side>>>(nullptr, outMu, outSig,
                                                      0, NSPLIT, H_DIM);

    // tgemm1-B on main (after chunk-B aggregate)
    tgemm_kernel<1><<<(N_NODES - NSPLIT + 127) / 128, 256>>>(nullptr, outMu, outSig,
                                                             NSPLIT, N_NODES, H_DIM);

    // Final join: side-stream output writes must precede stream end.
    cudaEventRecord(s_evTail, s_side);
    cudaStreamWaitEvent(0, s_evTail, 0);
}

// round 17
// speedup vs baseline: 1.0845x; 1.0845x over previous
#include <cuda_runtime.h>
#include <cuda_fp16.h>
#include <cstdint>

// Problem constants (fixed shapes per reference)
#define N_NODES 100000
#define N_NODES4 (N_NODES / 4)     // 25000 int4 chunks (N_NODES % 4 == 0)
#define F_IN    256
#define H_DIM   128
#define D_DIM   64
#define MAX_E   1700000

// ---------------- scratch (device globals; no allocation allowed) -------------
__device__ __align__(16) int    g_cnt [N_NODES];             // per-dst edge count / fill cursor
__device__ __align__(16) int    g_row [N_NODES + 4];         // CSR row offsets (pad for int4)
__device__ __align__(16) float  g_dinv[N_NODES];             // rsqrt(deg) incl self-loop
__device__ __align__(16) int2   g_csr [MAX_E];               // {src, norm-as-int-bits}
__device__ __align__(16) __half g_h1  [N_NODES * H_DIM];     // x @ W1        (fp16)
__device__ __align__(16) __half g_h2  [N_NODES * H_DIM];     // relu(agg1+b1) (fp16)
__device__ __align__(16) __half g_agg2[N_NODES * H_DIM];     // aggregated h2 (fp16)
__device__ __align__(16) float  g_bc  [128];                 // [bmu | bvar]
// Precomputed B fragments for m16n8k16 fp16 mma (2-split hi/lo):
//   index = (kstep16*16 + ntile)*32 + lane, value = {bh0, bh1, bl0, bl1} (f16x2 each)
__device__ __align__(16) uint4 g_Bf1[16 * 16 * 32];          // W1:  K=256 -> 16 ksteps
__device__ __align__(16) uint4 g_Bf2[ 8 * 16 * 32];          // Wc:  K=128 ->  8 ksteps

// ---------------- fp16 pack/unpack helpers ---------------------------------------
__device__ __forceinline__ float4 h4_to_f4(uint2 u) {
    float2 f0 = __half22float2(*(const __half2*)&u.x);
    float2 f1 = __half22float2(*(const __half2*)&u.y);
    return make_float4(f0.x, f0.y, f1.x, f1.y);
}
__device__ __forceinline__ uint2 f4_to_h4(float4 v) {
    __half2 h0 = __floats2half2_rn(v.x, v.y);
    __half2 h1 = __floats2half2_rn(v.z, v.w);
    uint2 u;
    u.x = *(const uint32_t*)&h0;
    u.y = *(const uint32_t*)&h1;
    return u;
}
__device__ __forceinline__ uint32_t pack_h2(float x, float y) {
    __half2 h = __floats2half2_rn(x, y);
    return *(const uint32_t*)&h;
}

// ---------------- CSR build ------------------------------------------------------
__global__ void zero_cnt_kernel() {
    int i = blockIdx.x * blockDim.x + threadIdx.x;
    if (i < N_NODES4) ((int4*)g_cnt)[i] = make_int4(0, 0, 0, 0);
}

__global__ void count_kernel(const int* __restrict__ dst, int E) {
    int i = blockIdx.x * blockDim.x + threadIdx.x;
    if (i < E) atomicAdd(&g_cnt[dst[i]], 1);
}

// Single-block exclusive scan over g_cnt -> g_row (4 elems/thread, int4 I/O),
// plus dinv, plus cnt reset.
__global__ void scan_kernel() {            // <<<1, 1024>>>
    __shared__ int warp_sums[32];
    __shared__ int s_carry;
    const int tid = threadIdx.x, lane = tid & 31, wid = tid >> 5;
    if (tid == 0) s_carry = 0;
    __syncthreads();
    for (int base = 0; base < N_NODES4; base += 1024) {
        int i4 = base + tid;
        int4 v = make_int4(0, 0, 0, 0);
        if (i4 < N_NODES4) v = ((const int4*)g_cnt)[i4];
        int sum = v.x + v.y + v.z + v.w;
        // warp inclusive scan of per-thread sums
        int x = sum;
#pragma unroll
        for (int off = 1; off < 32; off <<= 1) {
            int t = __shfl_up_sync(0xffffffffu, x, off);
            if (lane >= off) x += t;
        }
        if (lane == 31) warp_sums[wid] = x;
        __syncthreads();
        if (wid == 0) {
            int y = warp_sums[lane];
#pragma unroll
            for (int off = 1; off < 32; off <<= 1) {
                int t = __shfl_up_sync(0xffffffffu, y, off);
                if (lane >= off) y += t;
            }
            warp_sums[lane] = y;
        }
        __syncthreads();
        int warp_off = (wid == 0) ? 0 : warp_sums[wid - 1];
        if (i4 < N_NODES4) {
            int e0 = s_carry + warp_off + x - sum;   // exclusive prefix for elem 0
            ((int4*)g_row)[i4] = make_int4(e0, e0 + v.x, e0 + v.x + v.y,
                                           e0 + v.x + v.y + v.z);
            ((float4*)g_dinv)[i4] = make_float4(
                rsqrtf((float)v.x + 1.0f), rsqrtf((float)v.y + 1.0f),
                rsqrtf((float)v.z + 1.0f), rsqrtf((float)v.w + 1.0f));
            ((int4*)g_cnt)[i4] = make_int4(0, 0, 0, 0);   // reset as fill cursor
        }
        __syncthreads();                            // all reads of s_carry done
        if (tid == 1023) s_carry += warp_sums[31];
        __syncthreads();
    }
    if (threadIdx.x == 0) g_row[N_NODES] = s_carry;
}

__global__ void fill_kernel(const int* __restrict__ src, const int* __restrict__ dst, int E) {
    int e = blockIdx.x * blockDim.x + threadIdx.x;
    if (e >= E) return;
    int s = src[e], d = dst[e];
    int pos = g_row[d] + atomicAdd(&g_cnt[d], 1);
    g_csr[pos] = make_int2(s, __float_as_int(g_dinv[s] * g_dinv[d]));
}

// ---------------- fp16 mma helper -------------------------------------------------
__device__ __forceinline__ void mma_f16(float* d, const uint32_t* a, uint32_t b0, uint32_t b1) {
    asm volatile(
        "mma.sync.aligned.m16n8k16.row.col.f32.f16.f16.f32 "
        "{%0,%1,%2,%3}, {%4,%5,%6,%7}, {%8,%9}, {%0,%1,%2,%3};"
        : "+f"(d[0]), "+f"(d[1]), "+f"(d[2]), "+f"(d[3])
        : "r"(a[0]), "r"(a[1]), "r"(a[2]), "r"(a[3]), "r"(b0), "r"(b1));
}

// ---------------- B fragment precompute ------------------------------------------
// m16n8k16 B fragment (col-major, B[k][n]): lane -> gid=lane>>2, tig=lane&3;
// b0 = {B[s*16+2tig][n], B[s*16+2tig+1][n]}, b1 = {B[s*16+8+2tig][n], B[+1][n]}.
__device__ __forceinline__ void pack_bfrag(uint4* out, int i, float b00, float b01,
                                           float b10, float b11) {
    __half h00 = __float2half_rn(b00), h01 = __float2half_rn(b01);
    __half h10 = __float2half_rn(b10), h11 = __float2half_rn(b11);
    uint32_t bh0 = pack_h2(__half2float(h00), __half2float(h01));
    uint32_t bh1 = pack_h2(__half2float(h10), __half2float(h11));
    uint32_t bl0 = pack_h2(b00 - __half2float(h00), b01 - __half2float(h01));
    uint32_t bl1 = pack_h2(b10 - __half2float(h10), b11 - __half2float(h11));
    out[i] = make_uint4(bh0, bh1, bl0, bl1);
}

__global__ void pack_bfrag1_kernel(const float* __restrict__ W1) {
    int i = blockIdx.x * blockDim.x + threadIdx.x;   // 0 .. 16*16*32-1
    if (i >= 16 * 16 * 32) return;
    int lane = i & 31, nt = (i >> 5) & 15, s = i >> 9;
    int gid = lane >> 2, tig = lane & 3;
    int n = nt * 8 + gid;
    int k0 = s * 16 + 2 * tig;
    int k1 = k0 + 8;
    pack_bfrag(g_Bf1, i,
               W1[(k0 + 0) * 128 + n], W1[(k0 + 1) * 128 + n],
               W1[(k1 + 0) * 128 + n], W1[(k1 + 1) * 128 + n]);
}

__global__ void pack_bfrag2_kernel(const float* __restrict__ Wmu, const float* __restrict__ Wvar,
                                   const float* __restrict__ bmu, const float* __restrict__ bvar) {
    int i = blockIdx.x * blockDim.x + threadIdx.x;
    if (i < 128) g_bc[i] = (i < D_DIM) ? bmu[i] : bvar[i - D_DIM];
    if (i >= 8 * 16 * 32) return;
    int lane = i & 31, nt = (i >> 5) & 15, s = i >> 9;
    int gid = lane >> 2, tig = lane & 3;
    int n = nt * 8 + gid;
    int k0 = s * 16 + 2 * tig;
    int k1 = k0 + 8;
    auto W = [&](int k) {
        return (n < D_DIM) ? Wmu[k * D_DIM + n] : Wvar[k * D_DIM + (n - D_DIM)];
    };
    pack_bfrag(g_Bf2, i, W(k0), W(k0 + 1), W(k1), W(k1 + 1));
}

// ---------------- 2-split FP16 tensor-core GEMM: C[M,128] = A[M,K] @ B[K,128] -----
// Block 128x128, 256 threads = 8 warps as 2(m) x 4(n); warp tile 64x32.
// BK=16 double-buffered A in smem, [kpair][row] layout (R13-proven path).
// MODE 0: A = x (fp32, 2-split Ah+Al, 3 mma) -> g_h1 (fp16).
// MODE 1: A = g_agg2 (fp16 exact: Al=0, 2 mma), +bias -> mu|sigma (fp32).
template <int MODE>
__global__ void __launch_bounds__(256, 2)
tgemm_kernel(const float* __restrict__ Ap,
             float* __restrict__ outMu, float* __restrict__ outSig,
             int M, int K) {
    __shared__ __align__(16) uint32_t Ah[2][8][136];   // [buf][kpair][row] f16x2
    __shared__ __align__(16) uint32_t Al[2][8][136];   // MODE 0 only

    const uint4* Bf = (MODE == 0) ? g_Bf1 : g_Bf2;

    const int tid    = threadIdx.x;
    const int lane   = tid & 31;
    const int wid    = tid >> 5;
    const int warp_m = wid >> 2;      // 0..1 (64 rows each)
    const int warp_n = wid & 3;       // 0..3 (32 cols each)
    const int gid    = lane >> 2;     // 0..7
    const int tig    = lane & 3;      // 0..3
    const int row0   = blockIdx.x * 128;

    float acc[4][4][4];
#pragma unroll
    for (int mt = 0; mt < 4; mt++)
#pragma unroll
        for (int nt = 0; nt < 4; nt++)
#pragma unroll
            for (int r = 0; r < 4; r++) acc[mt][nt][r] = 0.0f;

    // BK=16 tile: thread stages row r = tid>>1, k-octet q8 = (tid&1)*8 (kpairs kp0..+3).
    auto load_tile = [&](int k0, int buf) {
        int r = tid >> 1, q8 = (tid & 1) * 8;
        int kp0 = q8 >> 1;                       // 0 or 4
        int gr = row0 + r;
        if (MODE == 0) {
            float4 va0 = make_float4(0.f, 0.f, 0.f, 0.f);
            float4 va1 = make_float4(0.f, 0.f, 0.f, 0.f);
            if (gr < M) {
                const float* ap = &Ap[(size_t)gr * K + k0 + q8];
                va0 = *(const float4*)&ap[0];
                va1 = *(const float4*)&ap[4];
            }
            float av[8] = {va0.x, va0.y, va0.z, va0.w, va1.x, va1.y, va1.z, va1.w};
#pragma unroll
            for (int jp = 0; jp < 4; jp++) {
                float x0 = av[2 * jp], x1 = av[2 * jp + 1];
                __half h0 = __float2half_rn(x0), h1 = __float2half_rn(x1);
                Ah[buf][kp0 + jp][r] = pack_h2(__half2float(h0), __half2float(h1));
                Al[buf][kp0 + jp][r] = pack_h2(x0 - __half2float(h0), x1 - __half2float(h1));
            }
        } else {
            uint4 v = make_uint4(0u, 0u, 0u, 0u);
            if (gr < M) v = *(const uint4*)&g_agg2[(size_t)gr * K + k0 + q8];
            Ah[buf][kp0 + 0][r] = v.x;
            Ah[buf][kp0 + 1][r] = v.y;
            Ah[buf][kp0 + 2][r] = v.z;
            Ah[buf][kp0 + 3][r] = v.w;
        }
    };

    const int steps = K / 16;
    load_tile(0, 0);
    __syncthreads();

    const uint4* BfW = Bf + (size_t)warp_n * 4 * 32 + lane;   // + s*16*32 + nt*32

    for (int s = 0; s < steps; s++) {
        uint4 fb[4];
#pragma unroll
        for (int nt = 0; nt < 4; nt++)
            fb[nt] = __ldg(&BfW[(size_t)s * 16 * 32 + nt * 32]);

        if (s + 1 < steps) load_tile((s + 1) * 16, (s + 1) & 1);
        const int cb = s & 1;

        uint32_t fah[4][4], fal[4][4];
#pragma unroll
        for (int mt = 0; mt < 4; mt++) {
            int m0 = warp_m * 64 + mt * 16;
            fah[mt][0] = Ah[cb][tig][m0 + gid];
            fah[mt][1] = Ah[cb][tig][m0 + 8 + gid];
            fah[mt][2] = Ah[cb][tig + 4][m0 + gid];
            fah[mt][3] = Ah[cb][tig + 4][m0 + 8 + gid];
            if (MODE == 0) {
                fal[mt][0] = Al[cb][tig][m0 + gid];
                fal[mt][1] = Al[cb][tig][m0 + 8 + gid];
                fal[mt][2] = Al[cb][tig + 4][m0 + gid];
                fal[mt][3] = Al[cb][tig + 4][m0 + 8 + gid];
            }
        }
#pragma unroll
        for (int mt = 0; mt < 4; mt++)
#pragma unroll
            for (int nt = 0; nt < 4; nt++) {
                mma_f16(acc[mt][nt], fah[mt], fb[nt].x, fb[nt].y);       // Ah*Bh
                mma_f16(acc[mt][nt], fah[mt], fb[nt].z, fb[nt].w);       // Ah*Bl
                if (MODE == 0)
                    mma_f16(acc[mt][nt], fal[mt], fb[nt].x, fb[nt].y);   // Al*Bh
            }
        __syncthreads();
    }

    // Epilogue. c0,c1 -> row gid, cols 2tig,2tig+1; c2,c3 -> row gid+8.
#pragma unroll
    for (int mt = 0; mt < 4; mt++) {
#pragma unroll
        for (int nt = 0; nt < 4; nt++) {
            int col = warp_n * 32 + nt * 8 + 2 * tig;
            int ra  = row0 + warp_m * 64 + mt * 16 + gid;
            int rb  = ra + 8;
            if (MODE == 0) {
                if (ra < M) *(__half2*)&g_h1[(size_t)ra * 128 + col] =
                    __floats2half2_rn(acc[mt][nt][0], acc[mt][nt][1]);
                if (rb < M) *(__half2*)&g_h1[(size_t)rb * 128 + col] =
                    __floats2half2_rn(acc[mt][nt][2], acc[mt][nt][3]);
            } else {
                float b0 = g_bc[col], b1 = g_bc[col + 1];
                float* baseA;
                float* baseB;
                if (col < 64) {
                    baseA = outMu + (size_t)ra * D_DIM + col;
                    baseB = outMu + (size_t)rb * D_DIM + col;
                } else {
                    baseA = outSig + (size_t)ra * D_DIM + (col - 64);
                    baseB = outSig + (size_t)rb * D_DIM + (col - 64);
                }
                if (ra < M) *(float2*)baseA =
                    make_float2(acc[mt][nt][0] + b0, acc[mt][nt][1] + b1);
                if (rb < M) *(float2*)baseB =
                    make_float2(acc[mt][nt][2] + b0, acc[mt][nt][3] + b1);
            }
        }
    }
}

// ---------------- CSR gather-aggregate (fp16 h rows, fp32 accumulate) -------------
// One warp per node; each lane covers 4 features (8B fp16 load per row).
// LAYER 0: reads g_h1, writes g_h2 = relu(agg + b1) as fp16 (relu fused)
// LAYER 1: reads g_h2, writes g_agg2 as fp16 (feeds GEMM2).
template <int LAYER>
__global__ void __launch_bounds__(256)
aggregate_kernel(const float* __restrict__ b1) {
    int n    = (blockIdx.x * 256 + threadIdx.x) >> 5;
    int lane = threadIdx.x & 31;
    if (n >= N_NODES) return;

    const __half* h = (LAYER == 0) ? g_h1 : g_h2;

    float di = g_dinv[n];
    float d2 = di * di;
    float4 acc = h4_to_f4(__ldg(&((const uint2*)(h + (size_t)n * 128))[lane]));
    acc.x *= d2; acc.y *= d2; acc.z *= d2; acc.w *= d2;

    int r0 = g_row[n], r1 = g_row[n + 1];
    for (int base = r0; base < r1; base += 32) {
        int rem = min(r1 - base, 32);
        int2 ent = make_int2(0, 0);
        if (lane < rem) ent = g_csr[base + lane];

        int k = 0;
        for (; k + 4 <= rem; k += 4) {
            int   s0 = __shfl_sync(0xffffffffu, ent.x, k + 0);
            int   s1 = __shfl_sync(0xffffffffu, ent.x, k + 1);
            int   s2 = __shfl_sync(0xffffffffu, ent.x, k + 2);
            int   s3 = __shfl_sync(0xffffffffu, ent.x, k + 3);
            float w0 = __int_as_float(__shfl_sync(0xffffffffu, ent.y, k + 0));
            float w1 = __int_as_float(__shfl_sync(0xffffffffu, ent.y, k + 1));
            float w2 = __int_as_float(__shfl_sync(0xffffffffu, ent.y, k + 2));
            float w3 = __int_as_float(__shfl_sync(0xffffffffu, ent.y, k + 3));
            uint2 u0 = __ldg(&((const uint2*)(h + (size_t)s0 * 128))[lane]);
            uint2 u1 = __ldg(&((const uint2*)(h + (size_t)s1 * 128))[lane]);
            uint2 u2 = __ldg(&((const uint2*)(h + (size_t)s2 * 128))[lane]);
            uint2 u3 = __ldg(&((const uint2*)(h + (size_t)s3 * 128))[lane]);
            float4 v0 = h4_to_f4(u0);
            float4 v1 = h4_to_f4(u1);
            float4 v2 = h4_to_f4(u2);
            float4 v3 = h4_to_f4(u3);
            acc.x = fmaf(v0.x, w0, acc.x); acc.y = fmaf(v0.y, w0, acc.y);
            acc.z = fmaf(v0.z, w0, acc.z); acc.w = fmaf(v0.w, w0, acc.w);
            acc.x = fmaf(v1.x, w1, acc.x); acc.y = fmaf(v1.y, w1, acc.y);
            acc.z = fmaf(v1.z, w1, acc.z); acc.w = fmaf(v1.w, w1, acc.w);
            acc.x = fmaf(v2.x, w2, acc.x); acc.y = fmaf(v2.y, w2, acc.y);
            acc.z = fmaf(v2.z, w2, acc.z); acc.w = fmaf(v2.w, w2, acc.w);
            acc.x = fmaf(v3.x, w3, acc.x); acc.y = fmaf(v3.y, w3, acc.y);
            acc.z = fmaf(v3.z, w3, acc.z); acc.w = fmaf(v3.w, w3, acc.w);
        }
        for (; k < rem; k++) {
            int   s = __shfl_sync(0xffffffffu, ent.x, k);
            float w = __int_as_float(__shfl_sync(0xffffffffu, ent.y, k));
            float4 v = h4_to_f4(__ldg(&((const uint2*)(h + (size_t)s * 128))[lane]));
            acc.x = fmaf(v.x, w, acc.x); acc.y = fmaf(v.y, w, acc.y);
            acc.z = fmaf(v.z, w, acc.z); acc.w = fmaf(v.w, w, acc.w);
        }
    }

    if (LAYER == 0) {
        float4 b = ((const float4*)b1)[lane];
        acc.x = fmaxf(acc.x + b.x, 0.0f);
        acc.y = fmaxf(acc.y + b.y, 0.0f);
        acc.z = fmaxf(acc.z + b.z, 0.0f);
        acc.w = fmaxf(acc.w + b.w, 0.0f);
        ((uint2*)(g_h2 + (size_t)n * 128))[lane] = f4_to_h4(acc);
    } else {
        ((uint2*)(g_agg2 + (size_t)n * 128))[lane] = f4_to_h4(acc);
    }
}

// --------------------------------------------------------------------------------
extern "C" void kernel_launch(void* const* d_in, const int* in_sizes, int n_in,
                              void* d_out, int out_size) {
    const float* x    = (const float*)d_in[0];
    const int*   ei   = (const int*)d_in[1];     // edge_index: int32
    const float* W1   = (const float*)d_in[2];
    const float* b1   = (const float*)d_in[3];
    const float* Wmu  = (const float*)d_in[4];
    const float* bmu  = (const float*)d_in[5];
    const float* Wvar = (const float*)d_in[6];
    const float* bvar = (const float*)d_in[7];

    const int E = in_sizes[1] / 2;
    const int* src = ei;
    const int* dst = ei + E;

    float* outMu  = (float*)d_out;
    float* outSig = (float*)d_out + (size_t)N_NODES * D_DIM;

    const int aggBlocks = (N_NODES * 32 + 255) / 256;   // one warp per node

    // Side stream + fork/join events: created once, reused every call (the
    // captured graph is identical call-to-call; no device memory involved).
    static cudaStream_t s_side = nullptr;
    static cudaEvent_t  s_evFork = nullptr, s_evJoin = nullptr;
    if (s_side == nullptr) {
        cudaStreamCreateWithFlags(&s_side, cudaStreamNonBlocking);
        cudaEventCreateWithFlags(&s_evFork, cudaEventDisableTiming);
        cudaEventCreateWithFlags(&s_evJoin, cudaEventDisableTiming);
    }

    // Fork: CSR chain + projection pack on side stream, GEMM1 on main stream.
    cudaEventRecord(s_evFork, 0);
    cudaStreamWaitEvent(s_side, s_evFork, 0);

    pack_bfrag1_kernel<<<(16 * 16 * 32 + 255) / 256, 256>>>(W1);            // #1 main
    zero_cnt_kernel   <<<(N_NODES4 + 255) / 256, 256, 0, s_side>>>();       // #2 side
    count_kernel      <<<(E + 255) / 256, 256, 0, s_side>>>(dst, E);        // #3 side

    // #4 (ncu capture slot): layer-1 fp16 GEMM (h1) — overlaps the CSR chain
    tgemm_kernel<0><<<(N_NODES + 127) / 128, 256>>>(x, nullptr, nullptr, N_NODES, F_IN);

    scan_kernel       <<<1, 1024, 0, s_side>>>();                           // side
    fill_kernel       <<<(E + 255) / 256, 256, 0, s_side>>>(src, dst, E);   // side
    pack_bfrag2_kernel<<<(8 * 16 * 32 + 255) / 256, 256, 0, s_side>>>(Wmu, Wvar, bmu, bvar);

    // Join: aggregates need both h1 (main) and CSR (side).
    cudaEventRecord(s_evJoin, s_side);
    cudaStreamWaitEvent(0, s_evJoin, 0);

    // layer-1 aggregate + fused relu (writes h2, fp16)
    aggregate_kernel<0><<<aggBlocks, 256>>>(b1);

    // layer-2 aggregate (agg2, fp16)
    aggregate_kernel<1><<<aggBlocks, 256>>>(nullptr);

    // fused mu/sigma fp16 GEMM into d_out
    tgemm_kernel<1><<<(N_NODES + 127) / 128, 256>>>(nullptr, outMu, outSig, N_NODES, H_DIM);
}